// round 9
// baseline (speedup 1.0000x reference)
#include <cuda_runtime.h>

#define NT 128           // threads per block (one batch row per thread)
#define BTOT 32768
typedef unsigned long long u64;

// ---------------- scratch (allocation-free rule: __device__ globals) --------
static __device__ float g_hq[BTOT * 4];
static __device__ float g_hp[BTOT * 4];

// ---------------- f32x2 helpers ---------------------------------------------
__device__ __forceinline__ u64 splat2(float x) {
    u64 r;
    // volatile: forbid CSE from keeping all splats live (register pressure)
    asm volatile("mov.b64 %0, {%1, %1};" : "=l"(r) : "f"(x));
    return r;
}
__device__ __forceinline__ u64 fma2(u64 a, u64 b, u64 c) {
    u64 d;
    asm("fma.rn.f32x2 %0, %1, %2, %3;" : "=l"(d) : "l"(a), "l"(b), "l"(c));
    return d;
}
__device__ __forceinline__ void unpack2(u64 v, float& lo, float& hi) {
    asm("mov.b64 {%0, %1}, %2;" : "=f"(lo), "=f"(hi) : "l"(v));
}

// ---------------- fast activations (MUFU-based, ~1e-6 accurate) -------------
__device__ __forceinline__ float sigf(float x) {
    return __fdividef(1.0f, 1.0f + __expf(-x));
}
__device__ __forceinline__ float tanhfast(float x) {
    float e = __expf(2.0f * x);
    return 1.0f - __fdividef(2.0f, e + 1.0f);
}

// ---------------- shared-memory layout (floats) -----------------------------
// weights gate-interleaved: w4[k][j][{i,f,g,o}]  (all offsets 16B-aligned)
// One weight set per tower; tower ts at base sm + ts*W_TOTAL.
static const int OFF_WIH0 = 0;              // 50*25*4 = 5000
static const int OFF_WHH0 = 5000;           // 25*25*4 = 2500
static const int OFF_B0   = 7500;           // 100
static const int OFF_WIH1 = 7600;           // 25*10*4 = 1000
static const int OFF_WHH1 = 8600;           // 10*10*4 = 400
static const int OFF_B1   = 9000;           // 40
static const int OFF_WIH2 = 9040;           // 10*4*4 = 160
static const int OFF_WHH2 = 9200;           // 4*4*4 = 64
static const int OFF_B2   = 9264;           // 16
static const int W_TOTAL  = 9280;
static const int SMEM_BYTES = 2 * W_TOTAL * 4;   // 74,240 B -> 2 blocks/SM

// ---------------- weight packers --------------------------------------------
// src Wih: [4H, DIN] row-major (torch gate order i,f,g,o).
// dst[(k*H+j)*4+g] = src[(g*H+j)*DIN+k]
template <int DIN, int H>
__device__ void packw(float* dst, const float* __restrict__ src, int tid) {
    const int n = DIN * H * 4;
    for (int idx = tid; idx < n; idx += NT) {
        int g = idx & 3, jk = idx >> 2;
        int j = jk % H, k = jk / H;
        dst[idx] = src[(g * H + j) * DIN + k];
    }
}
template <int H>
__device__ void packb(float* dst, const float* __restrict__ src, int tid) {
    for (int idx = tid; idx < 4 * H; idx += NT) {
        int g = idx & 3, j = idx >> 2;
        dst[idx] = src[g * H + j];
    }
}

__device__ void pack_tower(float* base, const float* const* w, int tid) {
    packw<50, 25>(base + OFF_WIH0, w[0], tid);
    packw<25, 25>(base + OFF_WHH0, w[1], tid);
    packb<25>(base + OFF_B0, w[2], tid);
    packw<25, 10>(base + OFF_WIH1, w[3], tid);
    packw<10, 10>(base + OFF_WHH1, w[4], tid);
    packb<10>(base + OFF_B1, w[5], tid);
    packw<10, 4>(base + OFF_WIH2, w[6], tid);
    packw<4, 4>(base + OFF_WHH2, w[7], tid);
    packb<4>(base + OFF_B2, w[8], tid);
}

// ---------------- one LSTM layer step, register state, j-tiled --------------
// xs: DIN scalar inputs in registers (array ref, fully unrolled static idx).
// h/c: register state arrays. Weights from smem, gate-packed.
template <int DIN, int H, int JB, int NX>
__device__ __forceinline__ void step_reg(
    const float (&xs)[NX], float (&h)[H], float (&c)[H],
    const float* swih, const float* swhh, const float* sbias)
{
    float hold[H];
#pragma unroll
    for (int j = 0; j < H; j++) hold[j] = h[j];

    const ulonglong2* wih = reinterpret_cast<const ulonglong2*>(swih);
    const ulonglong2* whh = reinterpret_cast<const ulonglong2*>(swhh);
    const ulonglong2* bb  = reinterpret_cast<const ulonglong2*>(sbias);

#pragma unroll
    for (int jt = 0; jt < H; jt += JB) {
        u64 a01[JB], a23[JB];
#pragma unroll
        for (int jj = 0; jj < JB; jj++) {
            ulonglong2 b = bb[jt + jj];
            a01[jj] = b.x;                  // {acc_i, acc_f}
            a23[jj] = b.y;                  // {acc_g, acc_o}
        }
#pragma unroll
        for (int k = 0; k < DIN; k++) {
            u64 xv = splat2(xs[k]);
#pragma unroll
            for (int jj = 0; jj < JB; jj++) {
                ulonglong2 w = wih[k * H + jt + jj];   // LDS.128 broadcast
                a01[jj] = fma2(xv, w.x, a01[jj]);
                a23[jj] = fma2(xv, w.y, a23[jj]);
            }
        }
#pragma unroll
        for (int k = 0; k < H; k++) {
            u64 hv = splat2(hold[k]);
#pragma unroll
            for (int jj = 0; jj < JB; jj++) {
                ulonglong2 w = whh[k * H + jt + jj];
                a01[jj] = fma2(hv, w.x, a01[jj]);
                a23[jj] = fma2(hv, w.y, a23[jj]);
            }
        }
#pragma unroll
        for (int jj = 0; jj < JB; jj++) {
            float ai, af, ag, ao;
            unpack2(a01[jj], ai, af);
            unpack2(a23[jj], ag, ao);
            float cg = fmaf(sigf(af), c[jt + jj], sigf(ai) * tanhfast(ag));
            c[jt + jj] = cg;
            h[jt + jj] = sigf(ao) * tanhfast(cg);
        }
    }
}

// ---------------- merged dual-tower kernel ----------------------------------
// 256 blocks. Each thread: its p row (T=50) then its q row (T=12).
// Uniform work per thread -> single balanced wave.
__global__ void __launch_bounds__(NT)
towers_kernel(
    const float* __restrict__ q, const float* __restrict__ p,
    const float* qa0, const float* qa1, const float* qa2,
    const float* qa3, const float* qa4, const float* qa5,
    const float* qa6, const float* qa7, const float* qa8,
    const float* pa0, const float* pa1, const float* pa2,
    const float* pa3, const float* pa4, const float* pa5,
    const float* pa6, const float* pa7, const float* pa8)
{
    extern __shared__ float sm[];
    const int tid = threadIdx.x;
    const int row = blockIdx.x * NT + tid;

    {
        const float* pw[9] = {pa0, pa1, pa2, pa3, pa4, pa5, pa6, pa7, pa8};
        const float* qw[9] = {qa0, qa1, qa2, qa3, qa4, qa5, qa6, qa7, qa8};
        pack_tower(sm, pw, tid);                 // tower 0 = p
        pack_tower(sm + W_TOTAL, qw, tid);       // tower 1 = q
    }
    __syncthreads();

#pragma unroll 1
    for (int ts = 0; ts < 2; ts++) {
        const float* wbase = sm + ts * W_TOTAL;
        const int   T      = ts ? 12 : 50;
        const float* xrow  = (ts ? q : p) + (size_t)row * T * 50;
        float*      hout   = ts ? g_hq : g_hp;

        float h0[25], c0[25], h1[10], c1[10], h2[4], c2[4];
#pragma unroll
        for (int j = 0; j < 25; j++) { h0[j] = 0.0f; c0[j] = 0.0f; }
#pragma unroll
        for (int j = 0; j < 10; j++) { h1[j] = 0.0f; c1[j] = 0.0f; }
#pragma unroll
        for (int j = 0; j < 4; j++)  { h2[j] = 0.0f; c2[j] = 0.0f; }

#pragma unroll 1
        for (int t = 0; t < T; t++) {
            float xs[50];
            const float2* xp = reinterpret_cast<const float2*>(xrow + t * 50);
#pragma unroll
            for (int k2 = 0; k2 < 25; k2++) {
                float2 v = __ldg(xp + k2);
                xs[2 * k2]     = v.x;
                xs[2 * k2 + 1] = v.y;
            }
            step_reg<50, 25, 5>(xs, h0, c0,
                                wbase + OFF_WIH0, wbase + OFF_WHH0, wbase + OFF_B0);
            step_reg<25, 10, 5>(h0, h1, c1,
                                wbase + OFF_WIH1, wbase + OFF_WHH1, wbase + OFF_B1);
            step_reg<10, 4, 4>(h1, h2, c2,
                               wbase + OFF_WIH2, wbase + OFF_WHH2, wbase + OFF_B2);
        }

#pragma unroll
        for (int j = 0; j < 4; j++) hout[row * 4 + j] = h2[j];
    }
}

// ---------------- combine: scores -> softmax --------------------------------
__global__ void __launch_bounds__(256)
combine_kernel(const float* __restrict__ fW, const float* __restrict__ fb,
               float* __restrict__ out)
{
    int row = blockIdx.x * blockDim.x + threadIdx.x;
    float s0 = g_hq[row * 4 + 0] * g_hp[row * 4 + 0];
    float s1 = g_hq[row * 4 + 1] * g_hp[row * 4 + 1];
    float s2 = g_hq[row * 4 + 2] * g_hp[row * 4 + 2];
    float s3 = g_hq[row * 4 + 3] * g_hp[row * 4 + 3];
    float l0 = __ldg(fb + 0) + __ldg(fW + 0) * s0 + __ldg(fW + 1) * s1
                             + __ldg(fW + 2) * s2 + __ldg(fW + 3) * s3;
    float l1 = __ldg(fb + 1) + __ldg(fW + 4) * s0 + __ldg(fW + 5) * s1
                             + __ldg(fW + 6) * s2 + __ldg(fW + 7) * s3;
    float m = fmaxf(l0, l1);
    float e0 = __expf(l0 - m);
    float e1 = __expf(l1 - m);
    float inv = __fdividef(1.0f, e0 + e1);
    out[row * 2 + 0] = e0 * inv;
    out[row * 2 + 1] = e1 * inv;
}

// ---------------- launch ----------------------------------------------------
extern "C" void kernel_launch(void* const* d_in, const int* in_sizes, int n_in,
                              void* d_out, int out_size)
{
    const float* q  = (const float*)d_in[0];
    const float* p  = (const float*)d_in[1];
    const float* qw[9];
    const float* pw[9];
    for (int i = 0; i < 9; i++) qw[i] = (const float*)d_in[2 + i];
    for (int i = 0; i < 9; i++) pw[i] = (const float*)d_in[11 + i];
    const float* fW = (const float*)d_in[20];
    const float* fb = (const float*)d_in[21];
    float* out = (float*)d_out;

    cudaFuncSetAttribute(towers_kernel,
                         cudaFuncAttributeMaxDynamicSharedMemorySize, SMEM_BYTES);

    towers_kernel<<<BTOT / NT, NT, SMEM_BYTES>>>(
        q, p,
        qw[0], qw[1], qw[2], qw[3], qw[4], qw[5], qw[6], qw[7], qw[8],
        pw[0], pw[1], pw[2], pw[3], pw[4], pw[5], pw[6], pw[7], pw[8]);
    combine_kernel<<<BTOT / 256, 256>>>(fW, fb, out);
}